// round 2
// baseline (speedup 1.0000x reference)
#include <cuda_runtime.h>

#define T_LEN 1024
#define B_SZ  64
#define D_DIM 512
#define N_TAG 24
#define KK    (D_DIM / 2)    // 256 k-pairs

// Output layout (float32): decoded | pot | lens | trans
#define OFF_POT   (B_SZ * T_LEN)                     // 65536
#define OFF_LENS  (OFF_POT + B_SZ * T_LEN * N_TAG)   // 1638400
#define OFF_TRANS (OFF_LENS + B_SZ)                  // 1638464

typedef unsigned long long u64;

// Packed f32x2 FMA (sm_103a FFMA2 path — PTX only)
__device__ __forceinline__ u64 ffma2(u64 a, u64 b, u64 c) {
    u64 d;
    asm("fma.rn.f32x2 %0, %1, %2, %3;" : "=l"(d) : "l"(a), "l"(b), "l"(c));
    return d;
}

// ---------------------------------------------------------------------------
// Kernel A: pot = x @ W + b (+ boundaries). Register-tiled 4 rows x 6 tags
// per thread; W pre-packed in SMEM as (even-k, odd-k) u64 pairs.
// 256 threads = 64 row-groups x 4 tag-groups; 256 rows per block.
// ---------------------------------------------------------------------------
__global__ void __launch_bounds__(256)
gemm_pot_kernel(const float* __restrict__ x,
                const float* __restrict__ W,
                const float* __restrict__ bias,
                const float* __restrict__ lb,
                const float* __restrict__ rb,
                float* __restrict__ potOut) {
    __shared__ u64 Ws[N_TAG * KK];          // 48 KB
    float* Wsf = (float*)Ws;

    int tid = threadIdx.x;
    // Ws[n*KK + kk] = (W[2kk][n], W[2kk+1][n])
    for (int i = tid; i < N_TAG * KK * 2; i += 256) {
        int idx = i >> 1;
        int n   = idx >> 8;           // idx / KK
        int kk  = idx & (KK - 1);
        int k   = 2 * kk + (i & 1);
        Wsf[i] = W[k * N_TAG + n];
    }
    __syncthreads();

    int tg    = tid & 3;              // tag group: tags [6tg, 6tg+6)
    int rid   = tid >> 2;             // 0..63
    int rbase = blockIdx.x * 256 + rid * 4;

    const u64* xp = (const u64*)(x + (size_t)rbase * D_DIM);  // row stride KK u64
    const u64* wB = Ws + (tg * 6) * KK;

    u64 acc[4][6];
#pragma unroll
    for (int j = 0; j < 4; j++)
#pragma unroll
        for (int i = 0; i < 6; i++) acc[j][i] = 0ull;

#pragma unroll 4
    for (int kk = 0; kk < KK; kk++) {
        u64 xv0 = xp[kk];
        u64 xv1 = xp[KK + kk];
        u64 xv2 = xp[2 * KK + kk];
        u64 xv3 = xp[3 * KK + kk];
#pragma unroll
        for (int i = 0; i < 6; i++) {
            u64 wv = wB[i * KK + kk];
            acc[0][i] = ffma2(xv0, wv, acc[0][i]);
            acc[1][i] = ffma2(xv1, wv, acc[1][i]);
            acc[2][i] = ffma2(xv2, wv, acc[2][i]);
            acc[3][i] = ffma2(xv3, wv, acc[3][i]);
        }
    }

    // Epilogue
    float bb[6], lbb[6], rbb[6];
#pragma unroll
    for (int i = 0; i < 6; i++) {
        int n = tg * 6 + i;
        bb[i]  = bias[n];
        lbb[i] = lb[n];
        rbb[i] = rb[n];
    }
#pragma unroll
    for (int j = 0; j < 4; j++) {
        int r = rbase + j;
        int t = r & (T_LEN - 1);
        float* outp = potOut + (size_t)r * N_TAG + tg * 6;
#pragma unroll
        for (int i = 0; i < 6; i++) {
            float lo = __uint_as_float((unsigned)(acc[j][i] & 0xffffffffull));
            float hi = __uint_as_float((unsigned)(acc[j][i] >> 32));
            float s = lo + hi + bb[i];
            if (t == 0)         s += lbb[i];
            if (t == T_LEN - 1) s += rbb[i];
            outp[i] = s;
        }
    }
}

// ---------------------------------------------------------------------------
// Kernel B: Viterbi forward + backtrace. One warp per batch.
// Alpha broadcast via double-buffered SMEM (1 STS + 1 syncwarp + 6 LDS.128
// per step instead of 24 SHFLs). Backpointers in SMEM.
// ---------------------------------------------------------------------------
__global__ void __launch_bounds__(32, 1)
viterbi_kernel(const float* __restrict__ pot,
               const float* __restrict__ trans,
               float* __restrict__ decodedOut) {
    __shared__ __align__(16) float aBuf[2][32];
    __shared__ unsigned char bp_s[(T_LEN - 1) * N_TAG];   // 24552 B

    int b    = blockIdx.x;
    int lane = threadIdx.x;
    int ln   = lane < N_TAG ? lane : (N_TAG - 1);

    const float* potB = pot + (size_t)b * T_LEN * N_TAG;

    float tc[N_TAG];
#pragma unroll
    for (int m = 0; m < N_TAG; m++) tc[m] = trans[m * N_TAG + ln];

    float alpha = potB[ln];
    if (lane < N_TAG) aBuf[0][lane] = alpha;

    // pot pipeline, depth 4
    float p1 = potB[1 * N_TAG + ln];
    float p2 = potB[2 * N_TAG + ln];
    float p3 = potB[3 * N_TAG + ln];
    float p4 = potB[4 * N_TAG + ln];
    __syncwarp();

    for (int t = 1; t < T_LEN; t++) {
        float pcur = p1; p1 = p2; p2 = p3; p3 = p4;
        int tl = t + 4 < T_LEN ? t + 4 : T_LEN - 1;
        p4 = potB[tl * N_TAG + ln];

        int buf = (t - 1) & 1;
        const float4* ap = (const float4*)aBuf[buf];
        float4 a0 = ap[0], a1 = ap[1], a2 = ap[2], a3 = ap[3], a4 = ap[4], a5 = ap[5];

        float s[N_TAG];
        int   idx[N_TAG];
        s[0] = a0.x + tc[0];  s[1] = a0.y + tc[1];  s[2] = a0.z + tc[2];  s[3] = a0.w + tc[3];
        s[4] = a1.x + tc[4];  s[5] = a1.y + tc[5];  s[6] = a1.z + tc[6];  s[7] = a1.w + tc[7];
        s[8] = a2.x + tc[8];  s[9] = a2.y + tc[9];  s[10] = a2.z + tc[10]; s[11] = a2.w + tc[11];
        s[12] = a3.x + tc[12]; s[13] = a3.y + tc[13]; s[14] = a3.z + tc[14]; s[15] = a3.w + tc[15];
        s[16] = a4.x + tc[16]; s[17] = a4.y + tc[17]; s[18] = a4.z + tc[18]; s[19] = a4.w + tc[19];
        s[20] = a5.x + tc[20]; s[21] = a5.y + tc[21]; s[22] = a5.z + tc[22]; s[23] = a5.w + tc[23];
#pragma unroll
        for (int m = 0; m < N_TAG; m++) idx[m] = m;

        // Contiguous-range tournament: left side always covers strictly lower
        // original indices -> strict '>' keeps first-occurrence argmax ties.
#define VCMP(i, j) { bool g = s[j] > s[i]; s[i] = g ? s[j] : s[i]; idx[i] = g ? idx[j] : idx[i]; }
#pragma unroll
        for (int st = 1; st < N_TAG; st <<= 1) {
#pragma unroll
            for (int i = 0; i + st < N_TAG; i += 2 * st) VCMP(i, i + st)
        }
#undef VCMP

        alpha = s[0] + pcur;
        if (lane < N_TAG) {
            aBuf[buf ^ 1][lane] = alpha;
            bp_s[(t - 1) * N_TAG + lane] = (unsigned char)idx[0];
        }
        __syncwarp();
    }

    // last_tag = first-occurrence argmax over lanes 0..23
    float bv = __shfl_sync(0xffffffffu, alpha, 0);
    int   bt = 0;
#pragma unroll
    for (int m = 1; m < N_TAG; m++) {
        float v = __shfl_sync(0xffffffffu, alpha, m);
        if (v > bv) { bv = v; bt = m; }
    }

    if (lane == 0) {
        float* dec = decodedOut + (size_t)b * T_LEN;
        int tag = bt;
        dec[T_LEN - 1] = (float)tag;
        for (int t = T_LEN - 2; t >= 0; t--) {
            tag = bp_s[t * N_TAG + tag];
            dec[t] = (float)tag;
        }
    }
}

// ---------------------------------------------------------------------------
// Kernel C: lens and trans copy.
// ---------------------------------------------------------------------------
__global__ void tail_kernel(const float* __restrict__ trans,
                            float* __restrict__ out) {
    int i = threadIdx.x;
    if (i < B_SZ)          out[OFF_LENS + i]  = (float)T_LEN;
    if (i < N_TAG * N_TAG) out[OFF_TRANS + i] = trans[i];
}

// ---------------------------------------------------------------------------
extern "C" void kernel_launch(void* const* d_in, const int* in_sizes, int n_in,
                              void* d_out, int out_size) {
    const float* x     = (const float*)d_in[0];
    const float* W     = (const float*)d_in[1];
    const float* bias  = (const float*)d_in[2];
    const float* trans = (const float*)d_in[3];
    const float* lb    = (const float*)d_in[4];
    const float* rb    = (const float*)d_in[5];

    float* out = (float*)d_out;
    float* pot = out + OFF_POT;

    gemm_pot_kernel<<<(B_SZ * T_LEN) / 256, 256>>>(x, W, bias, lb, rb, pot);
    tail_kernel<<<1, 640>>>(trans, out);
    viterbi_kernel<<<B_SZ, 32>>>(pot, trans, out);
}

// round 4
// speedup vs baseline: 1.1808x; 1.1808x over previous
#include <cuda_runtime.h>

#define T_LEN 1024
#define B_SZ  64
#define D_DIM 512
#define N_TAG 24

// Output layout (float32): decoded | pot | lens | trans
#define OFF_POT   (B_SZ * T_LEN)                     // 65536
#define OFF_LENS  (OFF_POT + B_SZ * T_LEN * N_TAG)   // 1638400
#define OFF_TRANS (OFF_LENS + B_SZ)                  // 1638464

typedef unsigned long long u64;

// Packed f32x2 FMA (sm_103a FFMA2 — PTX only)
__device__ __forceinline__ u64 ffma2(u64 a, u64 b, u64 c) {
    u64 d;
    asm("fma.rn.f32x2 %0, %1, %2, %3;" : "=l"(d) : "l"(a), "l"(b), "l"(c));
    return d;
}

struct __align__(16) f4u { u64 lo, hi; };   // one LDS.128 = 2 k-pairs

// ---------------------------------------------------------------------------
// GEMM: pot = x @ W + b (+ boundaries at t==0 / t==T_LEN-1)
// Grid 512 x 128 threads. Block: 128 rows. Thread: rows (p, p+64) x 12 tags.
// x staged through SMEM (coalesced); W resident in SMEM (broadcast reads).
// ---------------------------------------------------------------------------
#define KT     32              // k-floats per x tile
#define NTILE  (D_DIM / KT)    // 16
#define XS_STRIDE 18           // u64 per row: 8 float4 data + 1 pad
#define WTAG_F4U (D_DIM / 4)   // f4u elements per tag row = 128  (512 floats)

extern __shared__ u64 dyn_smem[];

__global__ void __launch_bounds__(128)
gemm_pot_kernel(const float* __restrict__ x,
                const float* __restrict__ W,
                const float* __restrict__ bias,
                const float* __restrict__ lb,
                const float* __restrict__ rb,
                float* __restrict__ potOut) {
    u64* Ws = dyn_smem;                        // [24][256] u64 (tag-major)
    u64* xs = dyn_smem + N_TAG * (D_DIM / 2);  // [128][XS_STRIDE] u64
    float* Wsf = (float*)Ws;

    int tid = threadIdx.x;

    // Load W transposed: Wsf[n*512 + k] = W[k*24 + n] (coalesced global reads)
    for (int i = tid; i < D_DIM * N_TAG; i += 128) {
        int k = i / N_TAG;
        int n = i - k * N_TAG;
        Wsf[n * D_DIM + k] = W[i];
    }

    int p = tid & 63;           // row id within half-block
    int h = tid >> 6;           // tag half: tags [12h, 12h+12)
    int rowg = blockIdx.x * 128;

    const float4* x4g = (const float4*)x + (size_t)rowg * (D_DIM / 4);

    u64 acc[2][12];
#pragma unroll
    for (int j = 0; j < 2; j++)
#pragma unroll
        for (int i = 0; i < 12; i++) acc[j][i] = 0ull;

    const f4u* xrow0 = (const f4u*)(xs + p * XS_STRIDE);
    const f4u* xrow1 = (const f4u*)(xs + (p + 64) * XS_STRIDE);

    for (int kt = 0; kt < NTILE; kt++) {
        __syncthreads();   // xs readers of previous tile done; W ready (1st iter)
        // Stage x tile: 128 rows x 8 float4, fully coalesced
#pragma unroll
        for (int j = 0; j < 8; j++) {
            int idx = tid + j * 128;          // 0..1023
            int row = idx >> 3;
            int c   = idx & 7;
            float4 v = x4g[(size_t)row * (D_DIM / 4) + kt * 8 + c];
            *(float4*)(xs + row * XS_STRIDE + c * 2) = v;
        }
        __syncthreads();

        const f4u* wb = (const f4u*)(Ws + (h * 12) * (D_DIM / 2) + kt * (KT / 2));
#pragma unroll
        for (int kk2 = 0; kk2 < KT / 4; kk2++) {
            f4u xv0 = xrow0[kk2];
            f4u xv1 = xrow1[kk2];
#pragma unroll
            for (int i = 0; i < 12; i++) {
                f4u wv = wb[i * WTAG_F4U + kk2];   // FIXED: tag stride = 128 f4u
                acc[0][i] = ffma2(xv0.lo, wv.lo, acc[0][i]);
                acc[0][i] = ffma2(xv0.hi, wv.hi, acc[0][i]);
                acc[1][i] = ffma2(xv1.lo, wv.lo, acc[1][i]);
                acc[1][i] = ffma2(xv1.hi, wv.hi, acc[1][i]);
            }
        }
    }

    // Epilogue: fold halves, add bias/boundaries, vector stores
    float bb[12], lbb[12], rbb[12];
#pragma unroll
    for (int i = 0; i < 12; i++) {
        int n = h * 12 + i;
        bb[i]  = bias[n];
        lbb[i] = lb[n];
        rbb[i] = rb[n];
    }
#pragma unroll
    for (int j = 0; j < 2; j++) {
        int r = rowg + p + j * 64;
        int t = r & (T_LEN - 1);
        float v[12];
#pragma unroll
        for (int i = 0; i < 12; i++) {
            float lo = __uint_as_float((unsigned)(acc[j][i] & 0xffffffffull));
            float hi = __uint_as_float((unsigned)(acc[j][i] >> 32));
            float s = lo + hi + bb[i];
            if (t == 0)         s += lbb[i];
            if (t == T_LEN - 1) s += rbb[i];
            v[i] = s;
        }
        float4* outp = (float4*)(potOut + (size_t)r * N_TAG + h * 12);
        outp[0] = make_float4(v[0], v[1], v[2], v[3]);
        outp[1] = make_float4(v[4], v[5], v[6], v[7]);
        outp[2] = make_float4(v[8], v[9], v[10], v[11]);
    }
}

// ---------------------------------------------------------------------------
// Viterbi forward + backtrace. One warp per batch. No in-loop divergence.
// ---------------------------------------------------------------------------
__global__ void __launch_bounds__(32, 1)
viterbi_kernel(const float* __restrict__ pot,
               const float* __restrict__ trans,
               float* __restrict__ decodedOut) {
    __shared__ __align__(16) float aBuf[2][32];
    __shared__ unsigned char bp_s[(T_LEN - 1) * 32];   // padded stride 32

    int b    = blockIdx.x;
    int lane = threadIdx.x;
    int ln   = lane < N_TAG ? lane : (N_TAG - 1);

    const float* potB = pot + (size_t)b * T_LEN * N_TAG;

    float tc[N_TAG];
#pragma unroll
    for (int m = 0; m < N_TAG; m++) tc[m] = trans[m * N_TAG + ln];

    float alpha = potB[ln];
    aBuf[0][lane] = alpha;     // slots 24..31 never read

    float p1 = potB[1 * N_TAG + ln];
    float p2 = potB[2 * N_TAG + ln];
    float p3 = potB[3 * N_TAG + ln];
    float p4 = potB[4 * N_TAG + ln];
    __syncwarp();

    for (int t = 1; t < T_LEN; t++) {
        float pcur = p1; p1 = p2; p2 = p3; p3 = p4;
        int tl = t + 4 < T_LEN ? t + 4 : T_LEN - 1;
        p4 = potB[tl * N_TAG + ln];

        int buf = (t - 1) & 1;
        const float4* ap = (const float4*)aBuf[buf];
        float4 a0 = ap[0], a1 = ap[1], a2 = ap[2], a3 = ap[3], a4 = ap[4], a5 = ap[5];

        float s[N_TAG];
        int   idx[N_TAG];
        s[0]  = a0.x + tc[0];  s[1]  = a0.y + tc[1];  s[2]  = a0.z + tc[2];  s[3]  = a0.w + tc[3];
        s[4]  = a1.x + tc[4];  s[5]  = a1.y + tc[5];  s[6]  = a1.z + tc[6];  s[7]  = a1.w + tc[7];
        s[8]  = a2.x + tc[8];  s[9]  = a2.y + tc[9];  s[10] = a2.z + tc[10]; s[11] = a2.w + tc[11];
        s[12] = a3.x + tc[12]; s[13] = a3.y + tc[13]; s[14] = a3.z + tc[14]; s[15] = a3.w + tc[15];
        s[16] = a4.x + tc[16]; s[17] = a4.y + tc[17]; s[18] = a4.z + tc[18]; s[19] = a4.w + tc[19];
        s[20] = a5.x + tc[20]; s[21] = a5.y + tc[21]; s[22] = a5.z + tc[22]; s[23] = a5.w + tc[23];
#pragma unroll
        for (int m = 0; m < N_TAG; m++) idx[m] = m;

        // Contiguous-range tournament; strict '>' keeps first-occurrence ties.
#define VCMP(i, j) { bool g = s[j] > s[i]; s[i] = g ? s[j] : s[i]; idx[i] = g ? idx[j] : idx[i]; }
#pragma unroll
        for (int st = 1; st < N_TAG; st <<= 1) {
#pragma unroll
            for (int i = 0; i + st < N_TAG; i += 2 * st) VCMP(i, i + st)
        }
#undef VCMP

        alpha = s[0] + pcur;
        aBuf[buf ^ 1][lane] = alpha;
        bp_s[(t - 1) * 32 + lane] = (unsigned char)idx[0];
        __syncwarp();
    }

    // last_tag = first-occurrence argmax over lanes 0..23
    float bv = __shfl_sync(0xffffffffu, alpha, 0);
    int   bt = 0;
#pragma unroll
    for (int m = 1; m < N_TAG; m++) {
        float v = __shfl_sync(0xffffffffu, alpha, m);
        if (v > bv) { bv = v; bt = m; }
    }

    if (lane == 0) {
        float* dec = decodedOut + (size_t)b * T_LEN;
        int tag = bt;
        dec[T_LEN - 1] = (float)tag;
        for (int t = T_LEN - 2; t >= 0; t--) {
            tag = bp_s[t * 32 + tag];
            dec[t] = (float)tag;
        }
    }
}

// ---------------------------------------------------------------------------
__global__ void tail_kernel(const float* __restrict__ trans,
                            float* __restrict__ out) {
    int i = threadIdx.x;
    if (i < B_SZ)          out[OFF_LENS + i]  = (float)T_LEN;
    if (i < N_TAG * N_TAG) out[OFF_TRANS + i] = trans[i];
}

// ---------------------------------------------------------------------------
extern "C" void kernel_launch(void* const* d_in, const int* in_sizes, int n_in,
                              void* d_out, int out_size) {
    const float* x     = (const float*)d_in[0];
    const float* W     = (const float*)d_in[1];
    const float* bias  = (const float*)d_in[2];
    const float* trans = (const float*)d_in[3];
    const float* lb    = (const float*)d_in[4];
    const float* rb    = (const float*)d_in[5];

    float* out = (float*)d_out;
    float* pot = out + OFF_POT;

    int smem_bytes = (N_TAG * (D_DIM / 2) + 128 * XS_STRIDE) * 8;  // 67584
    cudaFuncSetAttribute(gemm_pot_kernel,
                         cudaFuncAttributeMaxDynamicSharedMemorySize, smem_bytes);

    gemm_pot_kernel<<<512, 128, smem_bytes>>>(x, W, bias, lb, rb, pot);
    tail_kernel<<<1, 640>>>(trans, out);
    viterbi_kernel<<<B_SZ, 32>>>(pot, trans, out);
}

// round 5
// speedup vs baseline: 1.9504x; 1.6518x over previous
#include <cuda_runtime.h>
#include <cstdint>

#define T_LEN 1024
#define B_SZ  64
#define D_DIM 512
#define N_TAG 24

// Output layout (float32): decoded | pot | lens | trans
#define OFF_POT   (B_SZ * T_LEN)                     // 65536
#define OFF_LENS  (OFF_POT + B_SZ * T_LEN * N_TAG)   // 1638400
#define OFF_TRANS (OFF_LENS + B_SZ)                  // 1638464

typedef unsigned long long u64;

// Packed f32x2 FMA (sm_103a FFMA2 — PTX only)
__device__ __forceinline__ u64 ffma2(u64 a, u64 b, u64 c) {
    u64 d;
    asm("fma.rn.f32x2 %0, %1, %2, %3;" : "=l"(d) : "l"(a), "l"(b), "l"(c));
    return d;
}

struct __align__(16) f4u { u64 lo, hi; };   // one LDS.128 = 2 k-pairs

// ---------------------------------------------------------------------------
// GEMM: pot = x @ W + b (+ boundaries). Grid 256 x 128 threads (1 full wave
// at 2 blocks/SM). Block: 256 rows. Thread: 4 rows (p+64j) x 12 tags.
// Per kk2-chunk (4 k): 12 broadcast W-LDS.128 + 4 x-LDS.128 + 96 FFMA2.
// ---------------------------------------------------------------------------
#define KT     32              // k-floats per x tile
#define NTILE  (D_DIM / KT)    // 16
#define XS_STRIDE 18           // u64 per row: 8 float4 data + 1 pad
#define WTAG_F4U (D_DIM / 4)   // f4u per tag row = 128
#define ROWS_BLK 256

extern __shared__ u64 dyn_smem[];

__global__ void __launch_bounds__(128)
gemm_pot_kernel(const float* __restrict__ x,
                const float* __restrict__ W,
                const float* __restrict__ bias,
                const float* __restrict__ lb,
                const float* __restrict__ rb,
                float* __restrict__ potOut) {
    u64* Ws = dyn_smem;                        // [24][256] u64 (tag-major)
    u64* xs = dyn_smem + N_TAG * (D_DIM / 2);  // [256][XS_STRIDE] u64
    float* Wsf = (float*)Ws;

    int tid = threadIdx.x;

    // W transposed into SMEM: Wsf[n*512 + k] = W[k*24 + n] (coalesced LDG)
    for (int i = tid; i < D_DIM * N_TAG; i += 128) {
        int k = i / N_TAG;
        int n = i - k * N_TAG;
        Wsf[n * D_DIM + k] = W[i];
    }

    int p = tid & 63;           // base row id
    int h = tid >> 6;           // tag half: tags [12h, 12h+12)
    int rowg = blockIdx.x * ROWS_BLK;

    const float4* x4g = (const float4*)x + (size_t)rowg * (D_DIM / 4);

    u64 acc[4][12];
#pragma unroll
    for (int j = 0; j < 4; j++)
#pragma unroll
        for (int i = 0; i < 12; i++) acc[j][i] = 0ull;

    const f4u* xrow0 = (const f4u*)(xs + (p)       * XS_STRIDE);
    const f4u* xrow1 = (const f4u*)(xs + (p + 64)  * XS_STRIDE);
    const f4u* xrow2 = (const f4u*)(xs + (p + 128) * XS_STRIDE);
    const f4u* xrow3 = (const f4u*)(xs + (p + 192) * XS_STRIDE);
    const f4u* wb    = (const f4u*)(Ws + (h * 12) * (D_DIM / 2));

    for (int kt = 0; kt < NTILE; kt++) {
        __syncthreads();   // previous tile's readers done; W ready (1st iter)
        // Stage x tile: 256 rows x 8 float4, fully coalesced
#pragma unroll
        for (int j = 0; j < 16; j++) {
            int idx = tid + j * 128;          // 0..2047
            int row = idx >> 3;
            int c   = idx & 7;
            float4 v = x4g[(size_t)row * (D_DIM / 4) + kt * 8 + c];
            *(float4*)(xs + row * XS_STRIDE + c * 2) = v;
        }
        __syncthreads();

#pragma unroll
        for (int kk2 = 0; kk2 < KT / 4; kk2++) {
            f4u xv0 = xrow0[kk2];
            f4u xv1 = xrow1[kk2];
            f4u xv2 = xrow2[kk2];
            f4u xv3 = xrow3[kk2];
#pragma unroll
            for (int i = 0; i < 12; i++) {
                f4u wv = wb[i * WTAG_F4U + kt * 8 + kk2];
                acc[0][i] = ffma2(xv0.lo, wv.lo, acc[0][i]);
                acc[0][i] = ffma2(xv0.hi, wv.hi, acc[0][i]);
                acc[1][i] = ffma2(xv1.lo, wv.lo, acc[1][i]);
                acc[1][i] = ffma2(xv1.hi, wv.hi, acc[1][i]);
                acc[2][i] = ffma2(xv2.lo, wv.lo, acc[2][i]);
                acc[2][i] = ffma2(xv2.hi, wv.hi, acc[2][i]);
                acc[3][i] = ffma2(xv3.lo, wv.lo, acc[3][i]);
                acc[3][i] = ffma2(xv3.hi, wv.hi, acc[3][i]);
            }
        }
    }

    // Epilogue
    float bb[12], lbb[12], rbb[12];
#pragma unroll
    for (int i = 0; i < 12; i++) {
        int n = h * 12 + i;
        bb[i]  = bias[n];
        lbb[i] = lb[n];
        rbb[i] = rb[n];
    }
#pragma unroll
    for (int j = 0; j < 4; j++) {
        int r = rowg + p + j * 64;
        int t = r & (T_LEN - 1);
        float v[12];
#pragma unroll
        for (int i = 0; i < 12; i++) {
            float lo = __uint_as_float((unsigned)(acc[j][i] & 0xffffffffull));
            float hi = __uint_as_float((unsigned)(acc[j][i] >> 32));
            float s = lo + hi + bb[i];
            if (t == 0)         s += lbb[i];
            if (t == T_LEN - 1) s += rbb[i];
            v[i] = s;
        }
        float4* outp = (float4*)(potOut + (size_t)r * N_TAG + h * 12);
        outp[0] = make_float4(v[0], v[1], v[2], v[3]);
        outp[1] = make_float4(v[4], v[5], v[6], v[7]);
        outp[2] = make_float4(v[8], v[9], v[10], v[11]);
    }
}

// ---------------------------------------------------------------------------
// Viterbi. One warp per batch. pot streamed into SMEM via double-buffered
// cp.async chunks (64 steps each) so NO global load latency sits in the
// sequential chain. Broadcast via SHFL (self-syncing). Exact tournament.
// ---------------------------------------------------------------------------
#define CHUNK 64
#define NCHUNK (T_LEN / CHUNK)          // 16
#define CH_FLOATS (CHUNK * N_TAG)       // 1536 floats = 6144 B

__device__ __forceinline__ void cpasync16(uint32_t s, const void* g) {
    asm volatile("cp.async.cg.shared.global [%0], [%1], 16;" :: "r"(s), "l"(g));
}
__device__ __forceinline__ void cpcommit() {
    asm volatile("cp.async.commit_group;");
}
template <int N> __device__ __forceinline__ void cpwait() {
    asm volatile("cp.async.wait_group %0;" :: "n"(N));
}

__global__ void __launch_bounds__(32, 1)
viterbi_kernel(const float* __restrict__ pot,
               const float* __restrict__ trans,
               float* __restrict__ decodedOut) {
    __shared__ __align__(16) float potS[2][CH_FLOATS];       // 12288 B
    __shared__ unsigned char bp_s[(T_LEN - 1) * 32];         // 32736 B

    int b    = blockIdx.x;
    int lane = threadIdx.x;
    int ln   = lane < N_TAG ? lane : (N_TAG - 1);

    const float* potB = pot + (size_t)b * T_LEN * N_TAG;

    float tc[N_TAG];
#pragma unroll
    for (int m = 0; m < N_TAG; m++) tc[m] = trans[m * N_TAG + ln];

    uint32_t potS_addr = (uint32_t)__cvta_generic_to_shared(&potS[0][0]);

    // Issue chunk 0 and chunk 1
#pragma unroll
    for (int j = 0; j < 12; j++)
        cpasync16(potS_addr + j * 512 + lane * 16,
                  potB + j * 128 + lane * 4);
    cpcommit();
#pragma unroll
    for (int j = 0; j < 12; j++)
        cpasync16(potS_addr + 6144 + j * 512 + lane * 16,
                  potB + CH_FLOATS + j * 128 + lane * 4);
    cpcommit();
    cpwait<1>();          // chunk 0 landed
    __syncwarp();

    float alpha = potS[0][ln];    // t = 0

    for (int c = 0; c < NCHUNK; c++) {
        const float* pc = potS[c & 1];
        int tstart = (c == 0) ? 1 : 0;
        for (int tt = tstart; tt < CHUNK; tt++) {
            int t = c * CHUNK + tt;
            float pcur = pc[tt * N_TAG + ln];   // LDS, off critical path

            float s[N_TAG];
            int   idx[N_TAG];
#pragma unroll
            for (int m = 0; m < N_TAG; m++) {
                s[m]   = __shfl_sync(0xffffffffu, alpha, m) + tc[m];
                idx[m] = m;
            }

            // Contiguous-range tournament; strict '>' keeps first-occurrence
            // argmax tie semantics (left side covers strictly lower indices).
#define VCMP(i, j) { bool g = s[j] > s[i]; s[i] = g ? s[j] : s[i]; idx[i] = g ? idx[j] : idx[i]; }
#pragma unroll
            for (int st = 1; st < N_TAG; st <<= 1) {
#pragma unroll
                for (int i = 0; i + st < N_TAG; i += 2 * st) VCMP(i, i + st)
            }
#undef VCMP

            alpha = s[0] + pcur;
            bp_s[(t - 1) * 32 + lane] = (unsigned char)idx[0];
        }
        // Refill: issue chunk c+2 into the buffer we just finished reading
        if (c + 2 < NCHUNK) {
            uint32_t dst = potS_addr + (c & 1) * 6144;
            const float* src = potB + (size_t)(c + 2) * CH_FLOATS;
#pragma unroll
            for (int j = 0; j < 12; j++)
                cpasync16(dst + j * 512 + lane * 16, src + j * 128 + lane * 4);
            cpcommit();
            cpwait<1>();          // chunk c+1 ready
        } else {
            cpwait<0>();
        }
        __syncwarp();
    }

    // last_tag = first-occurrence argmax over lanes 0..23
    float bv = __shfl_sync(0xffffffffu, alpha, 0);
    int   bt = 0;
#pragma unroll
    for (int m = 1; m < N_TAG; m++) {
        float v = __shfl_sync(0xffffffffu, alpha, m);
        if (v > bv) { bv = v; bt = m; }
    }

    if (lane == 0) {
        float* dec = decodedOut + (size_t)b * T_LEN;
        int tag = bt;
        dec[T_LEN - 1] = (float)tag;
        for (int t = T_LEN - 2; t >= 0; t--) {
            tag = bp_s[t * 32 + tag];
            dec[t] = (float)tag;
        }
    }
}

// ---------------------------------------------------------------------------
__global__ void tail_kernel(const float* __restrict__ trans,
                            float* __restrict__ out) {
    int i = threadIdx.x;
    if (i < B_SZ)          out[OFF_LENS + i]  = (float)T_LEN;
    if (i < N_TAG * N_TAG) out[OFF_TRANS + i] = trans[i];
}

// ---------------------------------------------------------------------------
extern "C" void kernel_launch(void* const* d_in, const int* in_sizes, int n_in,
                              void* d_out, int out_size) {
    const float* x     = (const float*)d_in[0];
    const float* W     = (const float*)d_in[1];
    const float* bias  = (const float*)d_in[2];
    const float* trans = (const float*)d_in[3];
    const float* lb    = (const float*)d_in[4];
    const float* rb    = (const float*)d_in[5];

    float* out = (float*)d_out;
    float* pot = out + OFF_POT;

    int smem_bytes = (N_TAG * (D_DIM / 2) + ROWS_BLK * XS_STRIDE) * 8; // 86016
    cudaFuncSetAttribute(gemm_pot_kernel,
                         cudaFuncAttributeMaxDynamicSharedMemorySize, smem_bytes);

    gemm_pot_kernel<<<(B_SZ * T_LEN) / ROWS_BLK, 128, smem_bytes>>>(
        x, W, bias, lb, rb, pot);
    tail_kernel<<<1, 640>>>(trans, out);
    viterbi_kernel<<<B_SZ, 32>>>(pot, trans, out);
}